// round 12
// baseline (speedup 1.0000x reference)
#include <cuda_runtime.h>
#include <cuda_bf16.h>

#define NXv 432
#define NYv 496
#define CAPV (NXv * NYv)            // 214272 (NZ=1)
#define MAXP 100
#define NPTS_MAX 300000
#define NB 210                      // ceil(CAPV / 1024)

// ---- scratch (zero-init at load; k_copy tail restores the invariant that
// g_count / g_look are all-zero on entry). g_slots/g_feat/g_dst/g_cmeta need
// no cleaning: reads are always bounded by the current call's counters. ----
__device__ int g_count[CAPV];
__device__ int g_slots[CAPV * MAXP];         // per-voxel point-index slots (85.7 MB)
__device__ unsigned long long g_look[NB];    // decoupled-lookback words
__device__ int g_tot;                        // total occupied voxels
__device__ int g_totP;                       // total capped points
__device__ int4 g_cmeta[CAPV];               // per compact voxel: {lin, count, basP, 0}
__device__ float4 g_feat[NPTS_MAX];          // gathered features, compact order
__device__ int g_dst[NPTS_MAX];              // dest float4 offset in out voxel region

// Pack: bits[0:20)=capped-pts prefix, bits[20:40)=occ prefix,
// bits[62:64)=status (1=AGG, 2=PREFIX). totP<2^20, occ<2^20: fits.
__device__ __forceinline__ unsigned long long packLB(int st, int o, int p) {
    return ((unsigned long long)st << 62) |
           ((unsigned long long)(o & 0xFFFFF) << 20) |
           (unsigned long long)(p & 0xFFFFF);
}

// ---------------------------------------------------------------
// K_fill: pure streaming store — NO loads, NO metadata (R9 lesson).
__global__ void k_fill(float4* __restrict__ out, int n4, int cS4, int cE4) {
    int i = blockIdx.x * blockDim.x + threadIdx.x;
    if (i >= n4) return;
    float v = (i >= cS4 && i < cE4) ? -1.0f : 0.0f;
    out[i] = make_float4(v, v, v, v);
}

// K_bin: binning + fused slot scatter (arrival slot free from the counting
// atomic). NUMERICS LOCKED (R7): XLA rewrites /const into *reciprocal(const);
// fp32(1/0.16f)=6.25f exactly.
__global__ void k_bin(const float4* __restrict__ pts, int n) {
    int i = blockIdx.x * blockDim.x + threadIdx.x;
    if (i >= n) return;
    float4 p = pts[i];
    bool valid = (p.x >= 0.0f)    && (p.x < 69.12f) &&
                 (p.y >= -39.68f) && (p.y < 39.68f) &&
                 (p.z >= -3.0f)   && (p.z < 1.0f);
    if (!valid) return;
    float qx = __fmul_rn(__fsub_rn(p.x,   0.0f),  6.25f);
    float qy = __fmul_rn(__fsub_rn(p.y, -39.68f), 6.25f);
    int vx = min(max((int)floorf(qx), 0), NXv - 1);
    int vy = min(max((int)floorf(qy), 0), NYv - 1);
    int lin = vy * NXv + vx;          // vz always 0 (NZ=1; z-range validated)
    int slot = atomicAdd(&g_count[lin], 1);
    if (slot < MAXP) g_slots[lin * MAXP + slot] = i;
}

// K_scan: single-pass decoupled-lookback scan over (occupied, cappedCount).
// Emits compact metadata {lin, count, basP} in ascending-lin order + totals.
__global__ void k_scan() {
    __shared__ int wO[8], wP[8];
    __shared__ int sExc[2];
    int b = blockIdx.x, t = threadIdx.x;
    int lane = t & 31, warp = t >> 5;
    int e0 = b * 1024 + t * 4;
    int occ[4], cap[4], cnt[4];
    int so = 0, sp = 0;
#pragma unroll
    for (int j = 0; j < 4; j++) {
        int e = e0 + j;
        int c = (e < CAPV) ? g_count[e] : 0;
        cnt[j] = c;
        occ[j] = (c > 0) ? 1 : 0;
        cap[j] = (c < MAXP) ? c : MAXP;
        so += occ[j]; sp += cap[j];
    }
    int io = so, ip = sp;             // warp-inclusive scans
#pragma unroll
    for (int off = 1; off < 32; off <<= 1) {
        int vo = __shfl_up_sync(0xFFFFFFFFu, io, off);
        int vp = __shfl_up_sync(0xFFFFFFFFu, ip, off);
        if (lane >= off) { io += vo; ip += vp; }
    }
    if (lane == 31) { wO[warp] = io; wP[warp] = ip; }
    __syncthreads();
    if (warp == 0 && lane < 8) {
        int a = wO[lane], c2 = wP[lane];
#pragma unroll
        for (int off = 1; off < 8; off <<= 1) {
            int va = __shfl_up_sync(0xFFu, a,  off);
            int vc = __shfl_up_sync(0xFFu, c2, off);
            if (lane >= off) { a += va; c2 += vc; }
        }
        wO[lane] = a; wP[lane] = c2;
    }
    __syncthreads();
    int blkO = wO[7], blkP = wP[7];

    // ---- decoupled lookback (warp 0) ----
    if (t < 32) {
        if (lane == 0 && b > 0) {
            *(volatile unsigned long long*)(g_look + b) = packLB(1, blkO, blkP);
        }
        int accO = 0, accP = 0;
        if (b > 0) {
            int end = b;
            for (;;) {
                int idx = end - 1 - lane;
                unsigned long long v = 0;
                if (idx >= 0) {
                    volatile unsigned long long* vp = g_look + idx;
                    do { v = *vp; } while ((v >> 62) == 0ull);
                }
                bool isPref = (idx >= 0) && ((v >> 62) == 2ull);
                unsigned pm = __ballot_sync(0xFFFFFFFFu, isPref);
                int o  = (idx >= 0) ? (int)((v >> 20) & 0xFFFFF) : 0;
                int p2 = (idx >= 0) ? (int)(v & 0xFFFFF) : 0;
                if (pm) {
                    int fp = __ffs(pm) - 1;
                    if (lane > fp) { o = 0; p2 = 0; }
                }
#pragma unroll
                for (int off = 16; off; off >>= 1) {
                    o  += __shfl_down_sync(0xFFFFFFFFu, o,  off);
                    p2 += __shfl_down_sync(0xFFFFFFFFu, p2, off);
                }
                if (lane == 0) { accO += o; accP += p2; }
                if (pm) break;
                end -= 32;
            }
        }
        if (lane == 0) {
            sExc[0] = accO; sExc[1] = accP;
            *(volatile unsigned long long*)(g_look + b) =
                packLB(2, accO + blkO, accP + blkP);
            if (b == NB - 1) { g_tot = accO + blkO; g_totP = accP + blkP; }
        }
    }
    __syncthreads();

    int exO = sExc[0] + (warp ? wO[warp - 1] : 0) + (io - so);
    int exP = sExc[1] + (warp ? wP[warp - 1] : 0) + (ip - sp);
#pragma unroll
    for (int j = 0; j < 4; j++) {
        int e = e0 + j;
        if (e < CAPV && cnt[j] > 0) g_cmeta[exO] = make_int4(e, cnt[j], exP, 0);
        exO += occ[j]; exP += cap[j];
    }
}

// K_prep (hidden under the fill): per compact voxel, selection-sort the slot
// indices straight from global (NO local array — the R11 400B local array was
// the occupancy/latency killer), gather features into the dense compact
// buffer and record each element's final destination.
__global__ void k_prep(const float4* __restrict__ pts) {
    int i = blockIdx.x * blockDim.x + threadIdx.x;
    if (i >= g_tot) return;
    int4 m = g_cmeta[i];
    int lin = m.x, c = m.y, basP = m.z;
    int cc = (c < MAXP) ? c : MAXP;
    const int* __restrict__ srow = g_slots + (size_t)lin * MAXP;
    int prev = -1;
    int dst0 = i * MAXP;
    for (int r = 0; r < cc; r++) {     // cc avg ~1.7: O(cc^2) L1-resident scans
        int mn = 0x7FFFFFFF;
        for (int j = 0; j < cc; j++) {
            int v = srow[j];
            if (v > prev && v < mn) mn = v;
        }
        g_feat[basP + r] = pts[mn];
        g_dst[basP + r]  = dst0 + r;
        prev = mn;
    }
}

// K_copy (critical path after the fill): pure parallel placement — one
// load-pair, one store per capped point. Plus coords/counts and scratch
// cleanup in disjoint thread ranges.
__global__ void k_copy(float4* __restrict__ out4, float* __restrict__ out,
                       int hasCoords, int hasCounts) {
    const long long voxFloats   = (long long)CAPV * MAXP * 4;
    const long long coordFloats = (long long)CAPV * 3;
    int t = blockIdx.x * blockDim.x + threadIdx.x;
    if (t < NPTS_MAX) {
        if (t < g_totP) out4[g_dst[t]] = g_feat[t];
    } else if (t < NPTS_MAX + CAPV) {
        int i = t - NPTS_MAX;
        if (i < g_tot) {
            int4 m = g_cmeta[i];
            int lin = m.x;
            int y = lin / NXv, x = lin - y * NXv;
            if (hasCoords) {
                float* cr = out + voxFloats + (size_t)i * 3;
                cr[0] = 0.0f; cr[1] = (float)y; cr[2] = (float)x;
            }
            if (hasCounts) out[voxFloats + coordFloats + i] = (float)m.y;
        }
    } else {
        int zi = t - NPTS_MAX - CAPV;
        const int q = CAPV / 4;               // 53568
        if (zi < q)           ((int4*)g_count)[zi] = make_int4(0, 0, 0, 0);
        else if (zi < q + NB) g_look[zi - q] = 0ull;
    }
}

extern "C" void kernel_launch(void* const* d_in, const int* in_sizes, int n_in,
                              void* d_out, int out_size) {
    const float4* pts = (const float4*)d_in[0];
    int n = in_sizes[0] / 4;
    if (n > NPTS_MAX) n = NPTS_MAX;

    const long long voxFloats   = (long long)CAPV * MAXP * 4;  // 85,708,800
    const long long coordFloats = (long long)CAPV * 3;         // 642,816
    const long long total = (long long)out_size;

    const int hasCoords = (total >= voxFloats + coordFloats) ? 1 : 0;
    const int hasCounts = (total >= voxFloats + coordFloats + CAPV) ? 1 : 0;
    const int n4  = (int)(total / 4);
    const int cS4 = hasCoords ? (int)(voxFloats / 4) : n4;
    const int cE4 = hasCoords ? (int)((voxFloats + coordFloats) / 4) : n4;

    const int T = 256;
    const int copyThreads = NPTS_MAX + CAPV + (CAPV / 4) + NB;

    // Side stream + fork/join events: created once on the first (correctness)
    // call, never during capture. Non-blocking to dodge legacy-stream syncs.
    static cudaStream_t s_side = nullptr;
    static cudaEvent_t  e_fork = nullptr, e_join = nullptr;
    if (s_side == nullptr) {
        cudaStreamCreateWithFlags(&s_side, cudaStreamNonBlocking);
        cudaEventCreateWithFlags(&e_fork, cudaEventDisableTiming);
        cudaEventCreateWithFlags(&e_join, cudaEventDisableTiming);
    }

    // Fork: bin -> scan -> prep on the side stream, hidden under the fill.
    cudaEventRecord(e_fork, 0);
    cudaStreamWaitEvent(s_side, e_fork, 0);
    k_bin <<<(n + T - 1) / T, T, 0, s_side>>>(pts, n);
    k_scan<<<NB, 256, 0, s_side>>>();
    k_prep<<<(CAPV + T - 1) / T, T, 0, s_side>>>(pts);
    cudaEventRecord(e_join, s_side);

    k_fill<<<(n4 + T - 1) / T, T>>>((float4*)d_out, n4, cS4, cE4);

    // Join: copy needs both the fill (it overwrites rows) and the prep data.
    cudaStreamWaitEvent(0, e_join, 0);
    k_copy<<<(copyThreads + T - 1) / T, T>>>((float4*)d_out, (float*)d_out,
                                             hasCoords, hasCounts);
}

// round 13
// speedup vs baseline: 1.0240x; 1.0240x over previous
#include <cuda_runtime.h>
#include <cuda_bf16.h>

#define NXv 432
#define NYv 496
#define CAPV (NXv * NYv)            // 214272 (NZ=1)
#define MAXP 100
#define NPTS_MAX 300000
#define NB 210                      // ceil(CAPV / 1024)

// ---- scratch (zero-init at load; k_place tail restores the invariant that
// g_count / g_look are all-zero on entry). g_slots / g_lin / g_voxid need no
// cleaning: reads are always bounded by / gated on this call's data. ----
__device__ int g_count[CAPV];
__device__ int g_slots[CAPV * MAXP];         // per-voxel point-index slots
__device__ int g_lin[NPTS_MAX];              // per-point lin (-1 = invalid)
__device__ int g_voxid[CAPV];                // packed: compactRow*256 + min(cnt,255)
__device__ unsigned long long g_look[NB];    // decoupled-lookback words

// Pack: bits[0:20)=occ prefix, bits[62:64)=status (1=AGG, 2=PREFIX)
__device__ __forceinline__ unsigned long long packLB(int st, int o) {
    return ((unsigned long long)st << 62) | (unsigned long long)(o & 0xFFFFF);
}

// ---------------------------------------------------------------
// K_fill: pure streaming store — NO loads, NO metadata (R9 lesson).
__global__ void k_fill(float4* __restrict__ out, int n4, int cS4, int cE4) {
    int i = blockIdx.x * blockDim.x + threadIdx.x;
    if (i >= n4) return;
    float v = (i >= cS4 && i < cE4) ? -1.0f : 0.0f;
    out[i] = make_float4(v, v, v, v);
}

// K_bin: binning + fused slot scatter (arrival slot free from the counting
// atomic). NUMERICS LOCKED (R7): XLA rewrites /const into *reciprocal(const);
// fp32(1/0.16f)=6.25f exactly.
__global__ void k_bin(const float4* __restrict__ pts, int n) {
    int i = blockIdx.x * blockDim.x + threadIdx.x;
    if (i >= n) return;
    float4 p = pts[i];
    bool valid = (p.x >= 0.0f)    && (p.x < 69.12f) &&
                 (p.y >= -39.68f) && (p.y < 39.68f) &&
                 (p.z >= -3.0f)   && (p.z < 1.0f);
    int lin = -1;
    if (valid) {
        float qx = __fmul_rn(__fsub_rn(p.x,   0.0f),  6.25f);
        float qy = __fmul_rn(__fsub_rn(p.y, -39.68f), 6.25f);
        int vx = min(max((int)floorf(qx), 0), NXv - 1);
        int vy = min(max((int)floorf(qy), 0), NYv - 1);
        lin = vy * NXv + vx;          // vz always 0 (NZ=1; z-range validated)
        int slot = atomicAdd(&g_count[lin], 1);
        if (slot < MAXP) g_slots[lin * MAXP + slot] = i;
    }
    g_lin[i] = lin;
}

// K_scan: single-pass decoupled-lookback scan of the occupied flag. Packs
// {compactRow, cnt} per occupied lin, and writes coords + counts DIRECTLY to
// the output (fill has already laid down the -1 / 0 padding).
__global__ void k_scan(float* __restrict__ out, int hasCoords, int hasCounts) {
    const long long voxFloats   = (long long)CAPV * MAXP * 4;
    const long long coordFloats = (long long)CAPV * 3;
    __shared__ int wO[8];
    __shared__ int sExc;
    int b = blockIdx.x, t = threadIdx.x;
    int lane = t & 31, warp = t >> 5;
    int e0 = b * 1024 + t * 4;
    int occ[4], cnt[4];
    int so = 0;
#pragma unroll
    for (int j = 0; j < 4; j++) {
        int e = e0 + j;
        int c = (e < CAPV) ? g_count[e] : 0;
        cnt[j] = c;
        occ[j] = (c > 0) ? 1 : 0;
        so += occ[j];
    }
    int io = so;
#pragma unroll
    for (int off = 1; off < 32; off <<= 1) {
        int vo = __shfl_up_sync(0xFFFFFFFFu, io, off);
        if (lane >= off) io += vo;
    }
    if (lane == 31) wO[warp] = io;
    __syncthreads();
    if (warp == 0 && lane < 8) {
        int a = wO[lane];
#pragma unroll
        for (int off = 1; off < 8; off <<= 1) {
            int va = __shfl_up_sync(0xFFu, a, off);
            if (lane >= off) a += va;
        }
        wO[lane] = a;
    }
    __syncthreads();
    int blkO = wO[7];

    // ---- decoupled lookback (warp 0) ----
    if (t < 32) {
        if (lane == 0 && b > 0)
            *(volatile unsigned long long*)(g_look + b) = packLB(1, blkO);
        int accO = 0;
        if (b > 0) {
            int end = b;
            for (;;) {
                int idx = end - 1 - lane;
                unsigned long long v = 0;
                if (idx >= 0) {
                    volatile unsigned long long* vp = g_look + idx;
                    do { v = *vp; } while ((v >> 62) == 0ull);
                }
                bool isPref = (idx >= 0) && ((v >> 62) == 2ull);
                unsigned pm = __ballot_sync(0xFFFFFFFFu, isPref);
                int o = (idx >= 0) ? (int)(v & 0xFFFFF) : 0;
                if (pm) {
                    int fp = __ffs(pm) - 1;
                    if (lane > fp) o = 0;
                }
#pragma unroll
                for (int off = 16; off; off >>= 1)
                    o += __shfl_down_sync(0xFFFFFFFFu, o, off);
                if (lane == 0) accO += o;
                if (pm) break;
                end -= 32;
            }
        }
        if (lane == 0) {
            sExc = accO;
            *(volatile unsigned long long*)(g_look + b) = packLB(2, accO + blkO);
        }
    }
    __syncthreads();

    int exO = sExc + (warp ? wO[warp - 1] : 0) + (io - so);
#pragma unroll
    for (int j = 0; j < 4; j++) {
        int e = e0 + j;
        if (e < CAPV && cnt[j] > 0) {
            int vox = exO;
            int cpk = (cnt[j] < 255) ? cnt[j] : 255;
            g_voxid[e] = vox * 256 + cpk;
            if (hasCoords) {
                int y = e / NXv, x = e - y * NXv;
                float* cr = out + voxFloats + (size_t)vox * 3;
                cr[0] = 0.0f; cr[1] = (float)y; cr[2] = (float)x;
            }
            if (hasCounts) out[voxFloats + coordFloats + vox] = (float)cnt[j];
        }
        exO += occ[j];
    }
}

// K_place: per-point stable placement — rank of point i within its voxel is
// the number of recorded slot indices smaller than i (equals the reference's
// stable-sort position; no sort needed). One scattered 16B store per point.
// Tail blocks restore the all-zero scratch invariant (safe: no k_place thread
// reads g_count — counts come packed in g_voxid).
__global__ void k_place(const float4* __restrict__ pts, float4* __restrict__ out4,
                        int n) {
    int i = blockIdx.x * blockDim.x + threadIdx.x;
    if (i < n) {
        int lin = g_lin[i];
        if (lin < 0) return;
        int info = g_voxid[lin];
        int vox = info >> 8;
        int cc  = info & 255;
        if (cc > MAXP) cc = MAXP;
        const int* __restrict__ srow = g_slots + (size_t)lin * MAXP;
        int rank = 0;
        for (int j = 0; j < cc; j++) rank += (srow[j] < i) ? 1 : 0;
        if (rank < MAXP) out4[(size_t)vox * MAXP + rank] = pts[i];
    } else {
        int zi = i - n;
        const int q = CAPV / 4;               // 53568
        if (zi < q)           ((int4*)g_count)[zi] = make_int4(0, 0, 0, 0);
        else if (zi < q + NB) g_look[zi - q] = 0ull;
    }
}

extern "C" void kernel_launch(void* const* d_in, const int* in_sizes, int n_in,
                              void* d_out, int out_size) {
    const float4* pts = (const float4*)d_in[0];
    int n = in_sizes[0] / 4;
    if (n > NPTS_MAX) n = NPTS_MAX;

    const long long voxFloats   = (long long)CAPV * MAXP * 4;  // 85,708,800
    const long long coordFloats = (long long)CAPV * 3;         // 642,816
    const long long total = (long long)out_size;

    const int hasCoords = (total >= voxFloats + coordFloats) ? 1 : 0;
    const int hasCounts = (total >= voxFloats + coordFloats + CAPV) ? 1 : 0;
    const int n4  = (int)(total / 4);
    const int cS4 = hasCoords ? (int)(voxFloats / 4) : n4;
    const int cE4 = hasCoords ? (int)((voxFloats + coordFloats) / 4) : n4;

    const int T = 256;
    const int placeThreads = n + (CAPV / 4) + NB;

    k_fill <<<(n4 + T - 1) / T, T>>>((float4*)d_out, n4, cS4, cE4);
    k_bin  <<<(n + T - 1) / T, T>>>(pts, n);
    k_scan <<<NB, 256>>>((float*)d_out, hasCoords, hasCounts);
    k_place<<<(placeThreads + T - 1) / T, T>>>(pts, (float4*)d_out, n);
}

// round 14
// speedup vs baseline: 1.1028x; 1.0769x over previous
#include <cuda_runtime.h>
#include <cuda_bf16.h>

#define NXv 432
#define NYv 496
#define CAPV (NXv * NYv)            // 214272 (NZ=1)
#define MAXP 100
#define NPTS_MAX 300000
#define NB 210                      // ceil(CAPV / 1024)
#define HOTS 8                      // hot slots per voxel (L2-resident table)

// ---- scratch (zero-init at load; k_place tail restores the invariant that
// g_count / g_look are all-zero on entry). Slot tables / g_lin / g_voxid need
// no cleaning: reads are always bounded by / gated on this call's data. ----
__device__ int g_count[CAPV];
__device__ int g_slotsA[CAPV * HOTS];         // hot slots: 6.9 MB -> L2-resident
__device__ int g_slotsB[CAPV * (MAXP - HOTS)];// cold overflow: ~0 traffic in practice
__device__ int g_lin[NPTS_MAX];               // per-point lin (-1 = invalid)
__device__ int g_voxid[CAPV];                 // packed: compactRow*256 + min(cnt,255)
__device__ unsigned long long g_look[NB];     // decoupled-lookback words

// Pack: bits[0:20)=occ prefix, bits[62:64)=status (1=AGG, 2=PREFIX)
__device__ __forceinline__ unsigned long long packLB(int st, int o) {
    return ((unsigned long long)st << 62) | (unsigned long long)(o & 0xFFFFF);
}

// ---------------------------------------------------------------
// K_fill: pure streaming store — NO loads, NO metadata (R9 lesson).
// 4 coalesced float4 stores per thread to amortize index math.
__global__ void k_fill(float4* __restrict__ out, int n4, int cS4, int cE4) {
    int base = blockIdx.x * (blockDim.x * 4) + threadIdx.x;
#pragma unroll
    for (int k = 0; k < 4; k++) {
        int i = base + k * 256;
        if (i < n4) {
            float v = (i >= cS4 && i < cE4) ? -1.0f : 0.0f;
            out[i] = make_float4(v, v, v, v);
        }
    }
}

// K_bin: binning + fused slot scatter (arrival slot free from the counting
// atomic). NUMERICS LOCKED (R7): XLA rewrites /const into *reciprocal(const);
// fp32(1/0.16f)=6.25f exactly.
__global__ void k_bin(const float4* __restrict__ pts, int n) {
    int i = blockIdx.x * blockDim.x + threadIdx.x;
    if (i >= n) return;
    float4 p = pts[i];
    bool valid = (p.x >= 0.0f)    && (p.x < 69.12f) &&
                 (p.y >= -39.68f) && (p.y < 39.68f) &&
                 (p.z >= -3.0f)   && (p.z < 1.0f);
    int lin = -1;
    if (valid) {
        float qx = __fmul_rn(__fsub_rn(p.x,   0.0f),  6.25f);
        float qy = __fmul_rn(__fsub_rn(p.y, -39.68f), 6.25f);
        int vx = min(max((int)floorf(qx), 0), NXv - 1);
        int vy = min(max((int)floorf(qy), 0), NYv - 1);
        lin = vy * NXv + vx;          // vz always 0 (NZ=1; z-range validated)
        int slot = atomicAdd(&g_count[lin], 1);
        if (slot < HOTS)      g_slotsA[lin * HOTS + slot] = i;
        else if (slot < MAXP) g_slotsB[lin * (MAXP - HOTS) + slot - HOTS] = i;
    }
    g_lin[i] = lin;
}

// K_scan: single-pass decoupled-lookback scan of the occupied flag. Packs
// {compactRow, cnt} per occupied lin, and writes coords + counts DIRECTLY to
// the output (fill has already laid down the -1 / 0 padding).
__global__ void k_scan(float* __restrict__ out, int hasCoords, int hasCounts) {
    const long long voxFloats   = (long long)CAPV * MAXP * 4;
    const long long coordFloats = (long long)CAPV * 3;
    __shared__ int wO[8];
    __shared__ int sExc;
    int b = blockIdx.x, t = threadIdx.x;
    int lane = t & 31, warp = t >> 5;
    int e0 = b * 1024 + t * 4;
    int occ[4], cnt[4];
    int so = 0;
#pragma unroll
    for (int j = 0; j < 4; j++) {
        int e = e0 + j;
        int c = (e < CAPV) ? g_count[e] : 0;
        cnt[j] = c;
        occ[j] = (c > 0) ? 1 : 0;
        so += occ[j];
    }
    int io = so;
#pragma unroll
    for (int off = 1; off < 32; off <<= 1) {
        int vo = __shfl_up_sync(0xFFFFFFFFu, io, off);
        if (lane >= off) io += vo;
    }
    if (lane == 31) wO[warp] = io;
    __syncthreads();
    if (warp == 0 && lane < 8) {
        int a = wO[lane];
#pragma unroll
        for (int off = 1; off < 8; off <<= 1) {
            int va = __shfl_up_sync(0xFFu, a, off);
            if (lane >= off) a += va;
        }
        wO[lane] = a;
    }
    __syncthreads();
    int blkO = wO[7];

    // ---- decoupled lookback (warp 0) ----
    if (t < 32) {
        if (lane == 0 && b > 0)
            *(volatile unsigned long long*)(g_look + b) = packLB(1, blkO);
        int accO = 0;
        if (b > 0) {
            int end = b;
            for (;;) {
                int idx = end - 1 - lane;
                unsigned long long v = 0;
                if (idx >= 0) {
                    volatile unsigned long long* vp = g_look + idx;
                    do { v = *vp; } while ((v >> 62) == 0ull);
                }
                bool isPref = (idx >= 0) && ((v >> 62) == 2ull);
                unsigned pm = __ballot_sync(0xFFFFFFFFu, isPref);
                int o = (idx >= 0) ? (int)(v & 0xFFFFF) : 0;
                if (pm) {
                    int fp = __ffs(pm) - 1;
                    if (lane > fp) o = 0;
                }
#pragma unroll
                for (int off = 16; off; off >>= 1)
                    o += __shfl_down_sync(0xFFFFFFFFu, o, off);
                if (lane == 0) accO += o;
                if (pm) break;
                end -= 32;
            }
        }
        if (lane == 0) {
            sExc = accO;
            *(volatile unsigned long long*)(g_look + b) = packLB(2, accO + blkO);
        }
    }
    __syncthreads();

    int exO = sExc + (warp ? wO[warp - 1] : 0) + (io - so);
#pragma unroll
    for (int j = 0; j < 4; j++) {
        int e = e0 + j;
        if (e < CAPV && cnt[j] > 0) {
            int vox = exO;
            int cpk = (cnt[j] < 255) ? cnt[j] : 255;
            g_voxid[e] = vox * 256 + cpk;
            if (hasCoords) {
                int y = e / NXv, x = e - y * NXv;
                float* cr = out + voxFloats + (size_t)vox * 3;
                cr[0] = 0.0f; cr[1] = (float)y; cr[2] = (float)x;
            }
            if (hasCounts) out[voxFloats + coordFloats + vox] = (float)cnt[j];
        }
        exO += occ[j];
    }
}

// K_place: per-point stable placement — rank of point i within its voxel is
// the number of recorded slot indices smaller than i (the reference's
// stable-sort position; no sort needed). Hot slots come from the L2-resident
// table; overflow beyond HOTS is statistically never taken. One scattered
// 16B store per point. Tail blocks restore the all-zero scratch invariant.
__global__ void k_place(const float4* __restrict__ pts, float4* __restrict__ out4,
                        int n) {
    int i = blockIdx.x * blockDim.x + threadIdx.x;
    if (i < n) {
        int lin = g_lin[i];
        if (lin < 0) return;
        int info = g_voxid[lin];
        int vox = info >> 8;
        int cc  = info & 255;
        if (cc > MAXP) cc = MAXP;
        int rank = 0;
        const int* __restrict__ rowA = g_slotsA + (size_t)lin * HOTS;
        int ccA = (cc < HOTS) ? cc : HOTS;
        for (int j = 0; j < ccA; j++) rank += (rowA[j] < i) ? 1 : 0;
        if (cc > HOTS) {
            const int* __restrict__ rowB = g_slotsB + (size_t)lin * (MAXP - HOTS);
            for (int j = 0; j < cc - HOTS; j++) rank += (rowB[j] < i) ? 1 : 0;
        }
        if (rank < MAXP) out4[(size_t)vox * MAXP + rank] = pts[i];
    } else {
        int zi = i - n;
        const int q = CAPV / 4;               // 53568
        if (zi < q)           ((int4*)g_count)[zi] = make_int4(0, 0, 0, 0);
        else if (zi < q + NB) g_look[zi - q] = 0ull;
    }
}

extern "C" void kernel_launch(void* const* d_in, const int* in_sizes, int n_in,
                              void* d_out, int out_size) {
    const float4* pts = (const float4*)d_in[0];
    int n = in_sizes[0] / 4;
    if (n > NPTS_MAX) n = NPTS_MAX;

    const long long voxFloats   = (long long)CAPV * MAXP * 4;  // 85,708,800
    const long long coordFloats = (long long)CAPV * 3;         // 642,816
    const long long total = (long long)out_size;

    const int hasCoords = (total >= voxFloats + coordFloats) ? 1 : 0;
    const int hasCounts = (total >= voxFloats + coordFloats + CAPV) ? 1 : 0;
    const int n4  = (int)(total / 4);
    const int cS4 = hasCoords ? (int)(voxFloats / 4) : n4;
    const int cE4 = hasCoords ? (int)((voxFloats + coordFloats) / 4) : n4;

    const int T = 256;
    const int placeThreads = n + (CAPV / 4) + NB;
    const int fillBlocks = (n4 + T * 4 - 1) / (T * 4);

    k_fill <<<fillBlocks, T>>>((float4*)d_out, n4, cS4, cE4);
    k_bin  <<<(n + T - 1) / T, T>>>(pts, n);
    k_scan <<<NB, 256>>>((float*)d_out, hasCoords, hasCounts);
    k_place<<<(placeThreads + T - 1) / T, T>>>(pts, (float4*)d_out, n);
}